// round 16
// baseline (speedup 1.0000x reference)
#include <cuda_runtime.h>
#include <cuda_fp16.h>
#include <cstdint>

// ===========================================================================
// Problem constants
// ===========================================================================
#define B_      128
#define RES_    25
#define D_      512
#define C_      64
#define N_      20
#define Q_      (B_ * RES_)      // 3200
#define M_ROWS  (C_ * N_)        // 1280
#define LAM     (20.0f / 512.0f)
#define ASCALE  2048.0f

// ===========================================================================
// Device scratch (allocation-free)
// ===========================================================================
__device__ float g_V[B_ * C_];            // 128 x 64 quadform sums
__device__ unsigned int g_ticket;         // last-CTA election counter
__device__ __half g_Ahi[M_ROWS * D_];     // G*2048 fp16 hi/lo planes (prep)
__device__ __half g_Alo[M_ROWS * D_];
__device__ __half g_Bf[Q_ * D_];          // x fp16 plane (convert)

// ===========================================================================
// PTX helpers
// ===========================================================================
__device__ __forceinline__ uint32_t smem_to_u32(const void* p) {
    uint32_t a;
    asm("{ .reg .u64 t; cvta.to.shared.u64 t, %1; cvt.u32.u64 %0, t; }"
        : "=r"(a) : "l"(p));
    return a;
}

#define CP_ASYNC16(dst_u32, src_ptr) \
    asm volatile("cp.async.cg.shared.global [%0], [%1], 16;" \
        :: "r"(dst_u32), "l"(src_ptr) : "memory")
#define CP_COMMIT() asm volatile("cp.async.commit_group;" ::: "memory")
#define CP_WAIT(n)  asm volatile("cp.async.wait_group %0;" :: "n"(n) : "memory")

__device__ __forceinline__ void ldsm_x4(uint32_t r[4], uint32_t addr) {
    asm volatile("ldmatrix.sync.aligned.m8n8.x4.shared.b16 {%0,%1,%2,%3}, [%4];"
        : "=r"(r[0]), "=r"(r[1]), "=r"(r[2]), "=r"(r[3]) : "r"(addr));
}

__device__ __forceinline__ void mma16816h(float c[4], const uint32_t a[4],
                                          uint32_t b0, uint32_t b1) {
    asm volatile(
        "mma.sync.aligned.m16n8k16.row.col.f32.f16.f16.f32 "
        "{%0,%1,%2,%3},{%4,%5,%6,%7},{%8,%9},{%0,%1,%2,%3};"
        : "+f"(c[0]), "+f"(c[1]), "+f"(c[2]), "+f"(c[3])
        : "r"(a[0]), "r"(a[1]), "r"(a[2]), "r"(a[3]), "r"(b0), "r"(b1));
}

// ===========================================================================
// Kernel 1: per-class prep (warp-coop Gram; GJ; S; Cholesky; fp16 G emit)
// (identical to R13 / the 69.7us run)
// ===========================================================================
#define PAD_D 516

__global__ __launch_bounds__(256) void prep_kernel(const float* __restrict__ high) {
    const int c = blockIdx.x;
    const int t = threadIdx.x;
    const int lane = t & 31;
    const int wid = t >> 5;

    __shared__ float sH[N_ * PAD_D];
    __shared__ float aug[N_][2 * N_ + 1];
    __shared__ float colk[N_];
    __shared__ float sS[N_][N_ + 1];

    const float4* H4 = reinterpret_cast<const float4*>(high + (size_t)c * N_ * D_);
    for (int idx = t; idx < N_ * D_ / 4; idx += 256) {
        int r = idx >> 7;
        int k4 = idx & 127;
        *reinterpret_cast<float4*>(&sH[r * PAD_D + k4 * 4]) = H4[idx];
    }
    for (int e = t; e < N_ * N_; e += 256) {
        int i = e / N_, j = e % N_;
        aug[i][N_ + j] = (i == j) ? 1.0f : 0.0f;
    }
    __syncthreads();

    for (int p = wid; p < 210; p += 8) {
        int i = 0, rem = p;
        while (rem >= N_ - i) { rem -= N_ - i; i++; }
        int j = i + rem;
        const float* ri = sH + i * PAD_D;
        const float* rj = sH + j * PAD_D;
        float s0 = 0.f, s1 = 0.f;
        #pragma unroll
        for (int k = 0; k < 8; k++) {
            s0 = fmaf(ri[lane + k * 64],      rj[lane + k * 64],      s0);
            s1 = fmaf(ri[lane + 32 + k * 64], rj[lane + 32 + k * 64], s1);
        }
        float s = s0 + s1;
        #pragma unroll
        for (int off = 16; off > 0; off >>= 1)
            s += __shfl_xor_sync(0xffffffffu, s, off);
        if (lane == 0) {
            float v = s + (i == j ? LAM : 0.0f);
            aug[i][j] = v;
            if (i != j) aug[j][i] = v;
        }
    }
    __syncthreads();

    for (int k = 0; k < N_; k++) {
        float pinv = 1.0f / aug[k][k];
        if (t < N_) colk[t] = aug[t][k];
        __syncthreads();
        if (t < 2 * N_) aug[k][t] *= pinv;
        __syncthreads();
        for (int e = t; e < N_ * 2 * N_; e += 256) {
            int i = e / (2 * N_), j = e % (2 * N_);
            if (i != k) aug[i][j] = fmaf(-colk[i], aug[k][j], aug[i][j]);
        }
        __syncthreads();
    }

    for (int e = t; e < N_ * N_; e += 256) {
        int i = e / N_, j = e % N_;
        float acc = 0.0f;
        #pragma unroll
        for (int k = 0; k < N_; k++) acc = fmaf(aug[i][N_ + k], aug[k][N_ + j], acc);
        sS[i][j] = aug[i][N_ + j] + LAM * acc;
    }
    __syncthreads();

    for (int k = 0; k < N_; k++) {
        if (t == 0) sS[k][k] = sqrtf(sS[k][k]);
        __syncthreads();
        if (t > k && t < N_) sS[t][k] /= sS[k][k];
        __syncthreads();
        for (int e = t; e < N_ * N_; e += 256) {
            int i = e / N_, j = e % N_;
            if (j > k && i >= j) sS[i][j] = fmaf(-sS[i][k], sS[j][k], sS[i][j]);
        }
        __syncthreads();
    }

    const int kd4 = (t & 127) * 4;
    const int ihalf = t >> 7;
    __half2* Ahi2 = reinterpret_cast<__half2*>(g_Ahi + (size_t)c * N_ * D_);
    __half2* Alo2 = reinterpret_cast<__half2*>(g_Alo + (size_t)c * N_ * D_);
    #pragma unroll
    for (int r = 0; r < 10; r++) {
        const int i = ihalf + 2 * r;
        float ax = 0.f, ay = 0.f, az = 0.f, aw = 0.f;
        for (int j = i; j < N_; j++) {
            float lji = sS[j][i];
            float4 h = *reinterpret_cast<const float4*>(&sH[j * PAD_D + kd4]);
            ax = fmaf(lji, h.x, ax);
            ay = fmaf(lji, h.y, ay);
            az = fmaf(lji, h.z, az);
            aw = fmaf(lji, h.w, aw);
        }
        ax *= ASCALE; ay *= ASCALE; az *= ASCALE; aw *= ASCALE;
        __half hx = __float2half_rn(ax);
        __half hy = __float2half_rn(ay);
        __half hz = __float2half_rn(az);
        __half hw = __float2half_rn(aw);
        const int base2 = (i * D_ + kd4) >> 1;
        Ahi2[base2 + 0] = __half2(hx, hy);
        Ahi2[base2 + 1] = __half2(hz, hw);
        Alo2[base2 + 0] = __half2(
            __float2half_rn(ax - __half2float(hx)),
            __float2half_rn(ay - __half2float(hy)));
        Alo2[base2 + 1] = __half2(
            __float2half_rn(az - __half2float(hz)),
            __float2half_rn(aw - __half2float(hw)));
    }
}

// ===========================================================================
// Kernel 2: fp32 x -> fp16 plane; block 0 zeroes g_V and the ticket.
// (identical to R13 / the 69.7us run, plus ticket reset)
// ===========================================================================
__global__ __launch_bounds__(256) void convert_kernel(const float* __restrict__ x)
{
    if (blockIdx.x == 0) {
        for (int i = threadIdx.x; i < B_ * C_; i += 256) g_V[i] = 0.0f;
        if (threadIdx.x == 0) g_ticket = 0u;
    }
    const int NB4 = Q_ * D_ / 4;
    int idx = blockIdx.x * 256 + threadIdx.x;
    const int stride = gridDim.x * 256;
    const float4* x4 = reinterpret_cast<const float4*>(x);
    __half2* b2 = reinterpret_cast<__half2*>(g_Bf);
    for (int i = idx; i < NB4; i += stride) {
        float4 v = x4[i];
        b2[i * 2 + 0] = __half2(__float2half_rn(v.x), __float2half_rn(v.y));
        b2[i * 2 + 1] = __half2(__float2half_rn(v.z), __float2half_rn(v.w));
    }
}

// ===========================================================================
// Kernel 3: HMMA fp16x2 GEMM — ORIGINAL interleaved MMA order (the measured
// 42.1us schedule), fused V epilogue, last-CTA min-max output.
// ===========================================================================
#define BM   128
#define BN   128
#define BKc  32
#define NKC  (D_ / BKc)           // 16
#define ROWB 80
#define SZ_T (128 * ROWB)
#define SA_HI 0
#define SA_LO SZ_T
#define SB_F  (2 * SZ_T)
#define STG   (3 * SZ_T)          // 30720
#define SM_TOTAL (2 * STG)        // 61440
#define NBLOCKS ((Q_ / BN) * (M_ROWS / BM))   // 250

__global__ __launch_bounds__(256) void gemm_kernel(float* __restrict__ out) {
    extern __shared__ char sm[];
    __shared__ unsigned int sTicket;
    const uint32_t sb = smem_to_u32(sm);
    const int tid = threadIdx.x;
    const int lane = tid & 31;
    const int wid = tid >> 5;
    const int wm = wid & 3;
    const int wn = wid >> 2;
    const int m0 = blockIdx.y * BM;
    const int n0 = blockIdx.x * BN;

    float acc[2][8][4];
    #pragma unroll
    for (int i = 0; i < 2; i++)
        #pragma unroll
        for (int j = 0; j < 8; j++)
            #pragma unroll
            for (int k = 0; k < 4; k++) acc[i][j][k] = 0.0f;

    const int ar0 = tid >> 2;
    const int ac4 = (tid & 3) * 16;
    const int ak8 = (tid & 3) * 8;

    const int a_row  = wm * 32 + (lane & 15);
    const int a_kb   = ((lane >> 4) * 8) * 2;
    const uint32_t aoff = (uint32_t)(a_row * ROWB + a_kb);
    const int b_row  = wn * 64 + (lane & 7) + ((lane >> 4) * 8);
    const int b_kb   = (((lane >> 3) & 1) * 8) * 2;
    const uint32_t boff = (uint32_t)(b_row * ROWB + b_kb);

    auto load_stage = [&](int s, int kc) {
        const uint32_t base = sb + s * STG;
        const size_t kbase = (size_t)kc * BKc;
        #pragma unroll
        for (int p = 0; p < 2; p++) {
            int row = ar0 + p * 64;
            size_t ga = (size_t)(m0 + row) * D_ + kbase + ak8;
            size_t gb = (size_t)(n0 + row) * D_ + kbase + ak8;
            uint32_t soff = (uint32_t)(row * ROWB + ac4);
            CP_ASYNC16(base + SA_HI + soff, g_Ahi + ga);
            CP_ASYNC16(base + SA_LO + soff, g_Alo + ga);
            CP_ASYNC16(base + SB_F  + soff, g_Bf  + gb);
        }
    };

    load_stage(0, 0); CP_COMMIT();
    load_stage(1, 1); CP_COMMIT();

    for (int kc = 0; kc < NKC; kc++) {
        const int s = kc & 1;
        if (kc + 1 < NKC) { CP_WAIT(1); } else { CP_WAIT(0); }
        __syncthreads();

        const uint32_t base = sb + s * STG;
        #pragma unroll
        for (int ks = 0; ks < 2; ks++) {
            const uint32_t kb = ks * 32;
            uint32_t ah0[4], ah1[4], al0[4], al1[4];
            ldsm_x4(ah0, base + SA_HI + aoff + kb);
            ldsm_x4(ah1, base + SA_HI + aoff + 16 * ROWB + kb);
            ldsm_x4(al0, base + SA_LO + aoff + kb);
            ldsm_x4(al1, base + SA_LO + aoff + 16 * ROWB + kb);

            uint32_t Bf[8][2];
            #pragma unroll
            for (int g = 0; g < 4; g++) {
                uint32_t bf[4];
                ldsm_x4(bf, base + SB_F + boff + g * 16 * ROWB + kb);
                Bf[g * 2 + 0][0] = bf[0]; Bf[g * 2 + 0][1] = bf[1];
                Bf[g * 2 + 1][0] = bf[2]; Bf[g * 2 + 1][1] = bf[3];
            }

            #pragma unroll
            for (int nt = 0; nt < 8; nt++) {
                mma16816h(acc[0][nt], ah0, Bf[nt][0], Bf[nt][1]);
                mma16816h(acc[1][nt], ah1, Bf[nt][0], Bf[nt][1]);
                mma16816h(acc[0][nt], al0, Bf[nt][0], Bf[nt][1]);
                mma16816h(acc[1][nt], al1, Bf[nt][0], Bf[nt][1]);
            }
        }
        __syncthreads();

        if (kc + 2 < NKC) { load_stage(s, kc + 2); CP_COMMIT(); }
    }

    // ---- fused epilogue: fold z^2 into (rowslot, bslot) register partials ----
    const float inv = 1.0f / ASCALE;
    const int gr = lane >> 2;
    const int gc = (lane & 3) * 2;
    const int colw = n0 + wn * 64;
    const int bmin = colw / RES_;
    const int roww = m0 + wm * 32;
    const int cmin = roww / N_;

    float pr[4][4];
    #pragma unroll
    for (int i = 0; i < 4; i++)
        #pragma unroll
        for (int j = 0; j < 4; j++) pr[i][j] = 0.0f;

    #pragma unroll
    for (int mt = 0; mt < 2; mt++) {
        #pragma unroll
        for (int nt = 0; nt < 8; nt++) {
            const int c0 = colw + nt * 8 + gc;
            const int b0i = c0 / RES_ - bmin;
            const int b1i = (c0 + 1) / RES_ - bmin;
            #pragma unroll
            for (int k = 0; k < 4; k++) {
                float z = acc[mt][nt][k] * inv;
                float z2 = z * z;
                const int bi = (k & 1) ? b1i : b0i;
                #pragma unroll
                for (int bs = 0; bs < 4; bs++)
                    pr[mt * 2 + (k >> 1)][bs] += (bi == bs) ? z2 : 0.0f;
            }
        }
    }

    float pc[3][4];
    #pragma unroll
    for (int i = 0; i < 3; i++)
        #pragma unroll
        for (int j = 0; j < 4; j++) pc[i][j] = 0.0f;
    #pragma unroll
    for (int slot = 0; slot < 4; slot++) {
        const int row = roww + (slot >> 1) * 16 + (slot & 1) * 8 + gr;
        const int ci = row / N_ - cmin;
        #pragma unroll
        for (int cs = 0; cs < 3; cs++)
            #pragma unroll
            for (int bs = 0; bs < 4; bs++)
                pc[cs][bs] += (ci == cs) ? pr[slot][bs] : 0.0f;
    }

    #pragma unroll
    for (int cs = 0; cs < 3; cs++) {
        #pragma unroll
        for (int bs = 0; bs < 4; bs++) {
            float v = pc[cs][bs];
            #pragma unroll
            for (int off = 16; off > 0; off >>= 1)
                v += __shfl_xor_sync(0xffffffffu, v, off);
            if (lane == 0) {
                const int c = cmin + cs;
                const int bb = bmin + bs;
                if (c < C_ && bb < B_ && v != 0.0f)
                    atomicAdd(&g_V[bb * C_ + c], v);
            }
        }
    }

    // ---- last-CTA min-max + output ----
    __threadfence();
    __syncthreads();
    if (tid == 0) sTicket = atomicAdd(&g_ticket, 1u);
    __syncthreads();
    if (sTicket == NBLOCKS - 1) {
        for (int b = wid; b < B_; b += 8) {
            float v0 = __ldcg(&g_V[b * C_ + lane]);
            float v1 = __ldcg(&g_V[b * C_ + 32 + lane]);
            float mn = fminf(v0, v1), mx = fmaxf(v0, v1);
            #pragma unroll
            for (int off = 16; off > 0; off >>= 1) {
                mn = fminf(mn, __shfl_xor_sync(0xffffffffu, mn, off));
                mx = fmaxf(mx, __shfl_xor_sync(0xffffffffu, mx, off));
            }
            float inv2 = 1.0f / (mx - mn);
            out[b * C_ + lane]      = (v0 - mn) * inv2;
            out[b * C_ + 32 + lane] = (v1 - mn) * inv2;
        }
    }
}

// ===========================================================================
extern "C" void kernel_launch(void* const* d_in, const int* in_sizes, int n_in,
                              void* d_out, int out_size) {
    const float* x    = (const float*)d_in[0];   // (128, 25, 512)
    const float* high = (const float*)d_in[1];   // (64, 20, 512)
    float* out = (float*)d_out;                  // (128, 64)

    cudaFuncSetAttribute(gemm_kernel,
                         cudaFuncAttributeMaxDynamicSharedMemorySize, SM_TOTAL);

    convert_kernel<<<800, 256>>>(x);
    prep_kernel<<<C_, 256>>>(high);

    dim3 grid(Q_ / BN, M_ROWS / BM);             // (25, 10)
    gemm_kernel<<<grid, 256, SM_TOTAL>>>(out);
}

// round 17
// speedup vs baseline: 1.0574x; 1.0574x over previous
#include <cuda_runtime.h>
#include <cuda_fp16.h>
#include <cstdint>

// ===========================================================================
// Problem constants
// ===========================================================================
#define B_      128
#define RES_    25
#define D_      512
#define C_      64
#define N_      20
#define Q_      (B_ * RES_)      // 3200
#define M_ROWS  (C_ * N_)        // 1280
#define LAM     (20.0f / 512.0f)
#define ASCALE  2048.0f

// ===========================================================================
// Device scratch (allocation-free)
// ===========================================================================
__device__ float g_V[B_ * C_];            // 128 x 64 quadform sums
__device__ __half g_Ahi[M_ROWS * D_];     // G*2048 fp16 hi/lo planes (prep)
__device__ __half g_Alo[M_ROWS * D_];
__device__ __half g_Bf[Q_ * D_];          // x fp16 plane (convert)

// ===========================================================================
// PTX helpers
// ===========================================================================
__device__ __forceinline__ uint32_t smem_to_u32(const void* p) {
    uint32_t a;
    asm("{ .reg .u64 t; cvta.to.shared.u64 t, %1; cvt.u32.u64 %0, t; }"
        : "=r"(a) : "l"(p));
    return a;
}

#define CP_ASYNC16(dst_u32, src_ptr) \
    asm volatile("cp.async.cg.shared.global [%0], [%1], 16;" \
        :: "r"(dst_u32), "l"(src_ptr) : "memory")
#define CP_COMMIT() asm volatile("cp.async.commit_group;" ::: "memory")
#define CP_WAIT(n)  asm volatile("cp.async.wait_group %0;" :: "n"(n) : "memory")

__device__ __forceinline__ void ldsm_x4(uint32_t r[4], uint32_t addr) {
    asm volatile("ldmatrix.sync.aligned.m8n8.x4.shared.b16 {%0,%1,%2,%3}, [%4];"
        : "=r"(r[0]), "=r"(r[1]), "=r"(r[2]), "=r"(r[3]) : "r"(addr));
}

__device__ __forceinline__ void mma16816h(float c[4], const uint32_t a[4],
                                          uint32_t b0, uint32_t b1) {
    asm volatile(
        "mma.sync.aligned.m16n8k16.row.col.f32.f16.f16.f32 "
        "{%0,%1,%2,%3},{%4,%5,%6,%7},{%8,%9},{%0,%1,%2,%3};"
        : "+f"(c[0]), "+f"(c[1]), "+f"(c[2]), "+f"(c[3])
        : "r"(a[0]), "r"(a[1]), "r"(a[2]), "r"(a[3]), "r"(b0), "r"(b1));
}

// ===========================================================================
// Kernel 1: per-class prep (identical to the 69.7us R13 run)
// ===========================================================================
#define PAD_D 516

__global__ __launch_bounds__(256) void prep_kernel(const float* __restrict__ high) {
    const int c = blockIdx.x;
    const int t = threadIdx.x;
    const int lane = t & 31;
    const int wid = t >> 5;

    __shared__ float sH[N_ * PAD_D];
    __shared__ float aug[N_][2 * N_ + 1];
    __shared__ float colk[N_];
    __shared__ float sS[N_][N_ + 1];

    const float4* H4 = reinterpret_cast<const float4*>(high + (size_t)c * N_ * D_);
    for (int idx = t; idx < N_ * D_ / 4; idx += 256) {
        int r = idx >> 7;
        int k4 = idx & 127;
        *reinterpret_cast<float4*>(&sH[r * PAD_D + k4 * 4]) = H4[idx];
    }
    for (int e = t; e < N_ * N_; e += 256) {
        int i = e / N_, j = e % N_;
        aug[i][N_ + j] = (i == j) ? 1.0f : 0.0f;
    }
    __syncthreads();

    for (int p = wid; p < 210; p += 8) {
        int i = 0, rem = p;
        while (rem >= N_ - i) { rem -= N_ - i; i++; }
        int j = i + rem;
        const float* ri = sH + i * PAD_D;
        const float* rj = sH + j * PAD_D;
        float s0 = 0.f, s1 = 0.f;
        #pragma unroll
        for (int k = 0; k < 8; k++) {
            s0 = fmaf(ri[lane + k * 64],      rj[lane + k * 64],      s0);
            s1 = fmaf(ri[lane + 32 + k * 64], rj[lane + 32 + k * 64], s1);
        }
        float s = s0 + s1;
        #pragma unroll
        for (int off = 16; off > 0; off >>= 1)
            s += __shfl_xor_sync(0xffffffffu, s, off);
        if (lane == 0) {
            float v = s + (i == j ? LAM : 0.0f);
            aug[i][j] = v;
            if (i != j) aug[j][i] = v;
        }
    }
    __syncthreads();

    for (int k = 0; k < N_; k++) {
        float pinv = 1.0f / aug[k][k];
        if (t < N_) colk[t] = aug[t][k];
        __syncthreads();
        if (t < 2 * N_) aug[k][t] *= pinv;
        __syncthreads();
        for (int e = t; e < N_ * 2 * N_; e += 256) {
            int i = e / (2 * N_), j = e % (2 * N_);
            if (i != k) aug[i][j] = fmaf(-colk[i], aug[k][j], aug[i][j]);
        }
        __syncthreads();
    }

    for (int e = t; e < N_ * N_; e += 256) {
        int i = e / N_, j = e % N_;
        float acc = 0.0f;
        #pragma unroll
        for (int k = 0; k < N_; k++) acc = fmaf(aug[i][N_ + k], aug[k][N_ + j], acc);
        sS[i][j] = aug[i][N_ + j] + LAM * acc;
    }
    __syncthreads();

    for (int k = 0; k < N_; k++) {
        if (t == 0) sS[k][k] = sqrtf(sS[k][k]);
        __syncthreads();
        if (t > k && t < N_) sS[t][k] /= sS[k][k];
        __syncthreads();
        for (int e = t; e < N_ * N_; e += 256) {
            int i = e / N_, j = e % N_;
            if (j > k && i >= j) sS[i][j] = fmaf(-sS[i][k], sS[j][k], sS[i][j]);
        }
        __syncthreads();
    }

    const int kd4 = (t & 127) * 4;
    const int ihalf = t >> 7;
    __half2* Ahi2 = reinterpret_cast<__half2*>(g_Ahi + (size_t)c * N_ * D_);
    __half2* Alo2 = reinterpret_cast<__half2*>(g_Alo + (size_t)c * N_ * D_);
    #pragma unroll
    for (int r = 0; r < 10; r++) {
        const int i = ihalf + 2 * r;
        float ax = 0.f, ay = 0.f, az = 0.f, aw = 0.f;
        for (int j = i; j < N_; j++) {
            float lji = sS[j][i];
            float4 h = *reinterpret_cast<const float4*>(&sH[j * PAD_D + kd4]);
            ax = fmaf(lji, h.x, ax);
            ay = fmaf(lji, h.y, ay);
            az = fmaf(lji, h.z, az);
            aw = fmaf(lji, h.w, aw);
        }
        ax *= ASCALE; ay *= ASCALE; az *= ASCALE; aw *= ASCALE;
        __half hx = __float2half_rn(ax);
        __half hy = __float2half_rn(ay);
        __half hz = __float2half_rn(az);
        __half hw = __float2half_rn(aw);
        const int base2 = (i * D_ + kd4) >> 1;
        Ahi2[base2 + 0] = __half2(hx, hy);
        Ahi2[base2 + 1] = __half2(hz, hw);
        Alo2[base2 + 0] = __half2(
            __float2half_rn(ax - __half2float(hx)),
            __float2half_rn(ay - __half2float(hy)));
        Alo2[base2 + 1] = __half2(
            __float2half_rn(az - __half2float(hz)),
            __float2half_rn(aw - __half2float(hw)));
    }
}

// ===========================================================================
// Kernel 2: fp32 x -> fp16 plane; block 0 zeroes g_V.  (R13 exact)
// ===========================================================================
__global__ __launch_bounds__(256) void convert_kernel(const float* __restrict__ x)
{
    if (blockIdx.x == 0) {
        for (int i = threadIdx.x; i < B_ * C_; i += 256) g_V[i] = 0.0f;
    }
    const int NB4 = Q_ * D_ / 4;
    int idx = blockIdx.x * 256 + threadIdx.x;
    const int stride = gridDim.x * 256;
    const float4* x4 = reinterpret_cast<const float4*>(x);
    __half2* b2 = reinterpret_cast<__half2*>(g_Bf);
    for (int i = idx; i < NB4; i += stride) {
        float4 v = x4[i];
        b2[i * 2 + 0] = __half2(__float2half_rn(v.x), __float2half_rn(v.y));
        b2[i * 2 + 1] = __half2(__float2half_rn(v.z), __float2half_rn(v.w));
    }
}

// ===========================================================================
// Kernel 3: HMMA fp16x2 GEMM, 3-buffer / 2-in-flight cp.async pipeline with
// a SINGLE barrier per k-iteration, fused V epilogue (no fence, no ticket).
// ===========================================================================
#define BM   128
#define BN   128
#define BKc  32
#define NKC  (D_ / BKc)           // 16
#define ROWB 80
#define SZ_T (128 * ROWB)
#define SA_HI 0
#define SA_LO SZ_T
#define SB_F  (2 * SZ_T)
#define STG   (3 * SZ_T)          // 30720 per stage
#define NSTAGE 3
#define SM_TOTAL (NSTAGE * STG)   // 92160

__global__ __launch_bounds__(256) void gemm_kernel() {
    extern __shared__ char sm[];
    const uint32_t sb = smem_to_u32(sm);
    const int tid = threadIdx.x;
    const int lane = tid & 31;
    const int wid = tid >> 5;
    const int wm = wid & 3;
    const int wn = wid >> 2;
    const int m0 = blockIdx.y * BM;
    const int n0 = blockIdx.x * BN;

    float acc[2][8][4];
    #pragma unroll
    for (int i = 0; i < 2; i++)
        #pragma unroll
        for (int j = 0; j < 8; j++)
            #pragma unroll
            for (int k = 0; k < 4; k++) acc[i][j][k] = 0.0f;

    const int ar0 = tid >> 2;
    const int ac4 = (tid & 3) * 16;
    const int ak8 = (tid & 3) * 8;

    const int a_row  = wm * 32 + (lane & 15);
    const int a_kb   = ((lane >> 4) * 8) * 2;
    const uint32_t aoff = (uint32_t)(a_row * ROWB + a_kb);
    const int b_row  = wn * 64 + (lane & 7) + ((lane >> 4) * 8);
    const int b_kb   = (((lane >> 3) & 1) * 8) * 2;
    const uint32_t boff = (uint32_t)(b_row * ROWB + b_kb);

    auto load_stage = [&](int s, int kc) {
        const uint32_t base = sb + s * STG;
        const size_t kbase = (size_t)kc * BKc;
        #pragma unroll
        for (int p = 0; p < 2; p++) {
            int row = ar0 + p * 64;
            size_t ga = (size_t)(m0 + row) * D_ + kbase + ak8;
            size_t gb = (size_t)(n0 + row) * D_ + kbase + ak8;
            uint32_t soff = (uint32_t)(row * ROWB + ac4);
            CP_ASYNC16(base + SA_HI + soff, g_Ahi + ga);
            CP_ASYNC16(base + SA_LO + soff, g_Alo + ga);
            CP_ASYNC16(base + SB_F  + soff, g_Bf  + gb);
        }
    };

    // prologue: 2 tiles in flight, 3 buffers
    load_stage(0, 0); CP_COMMIT();
    load_stage(1, 1); CP_COMMIT();

    for (int kc = 0; kc < NKC; kc++) {
        const int s = kc % NSTAGE;
        if (kc + 1 < NKC) { CP_WAIT(1); } else { CP_WAIT(0); }
        __syncthreads();   // all warps done with stage (kc+2)%3 (tile kc-1)

        // issue next loads BEFORE compute (targets stage of tile kc-1, safe)
        if (kc + 2 < NKC) { load_stage((kc + 2) % NSTAGE, kc + 2); CP_COMMIT(); }

        const uint32_t base = sb + s * STG;
        #pragma unroll
        for (int ks = 0; ks < 2; ks++) {
            const uint32_t kb = ks * 32;
            uint32_t ah0[4], ah1[4], al0[4], al1[4];
            ldsm_x4(ah0, base + SA_HI + aoff + kb);
            ldsm_x4(ah1, base + SA_HI + aoff + 16 * ROWB + kb);
            ldsm_x4(al0, base + SA_LO + aoff + kb);
            ldsm_x4(al1, base + SA_LO + aoff + 16 * ROWB + kb);

            uint32_t Bf[8][2];
            #pragma unroll
            for (int g = 0; g < 4; g++) {
                uint32_t bf[4];
                ldsm_x4(bf, base + SB_F + boff + g * 16 * ROWB + kb);
                Bf[g * 2 + 0][0] = bf[0]; Bf[g * 2 + 0][1] = bf[1];
                Bf[g * 2 + 1][0] = bf[2]; Bf[g * 2 + 1][1] = bf[3];
            }

            #pragma unroll
            for (int nt = 0; nt < 8; nt++) {
                mma16816h(acc[0][nt], ah0, Bf[nt][0], Bf[nt][1]);
                mma16816h(acc[1][nt], ah1, Bf[nt][0], Bf[nt][1]);
                mma16816h(acc[0][nt], al0, Bf[nt][0], Bf[nt][1]);
                mma16816h(acc[1][nt], al1, Bf[nt][0], Bf[nt][1]);
            }
        }
    }

    // ---- fused epilogue: fold z^2 into (rowslot, bslot) register partials ----
    const float inv = 1.0f / ASCALE;
    const int gr = lane >> 2;
    const int gc = (lane & 3) * 2;
    const int colw = n0 + wn * 64;
    const int bmin = colw / RES_;
    const int roww = m0 + wm * 32;
    const int cmin = roww / N_;

    float pr[4][4];
    #pragma unroll
    for (int i = 0; i < 4; i++)
        #pragma unroll
        for (int j = 0; j < 4; j++) pr[i][j] = 0.0f;

    #pragma unroll
    for (int mt = 0; mt < 2; mt++) {
        #pragma unroll
        for (int nt = 0; nt < 8; nt++) {
            const int c0 = colw + nt * 8 + gc;
            const int b0i = c0 / RES_ - bmin;
            const int b1i = (c0 + 1) / RES_ - bmin;
            #pragma unroll
            for (int k = 0; k < 4; k++) {
                float z = acc[mt][nt][k] * inv;
                float z2 = z * z;
                const int bi = (k & 1) ? b1i : b0i;
                #pragma unroll
                for (int bs = 0; bs < 4; bs++)
                    pr[mt * 2 + (k >> 1)][bs] += (bi == bs) ? z2 : 0.0f;
            }
        }
    }

    float pc[3][4];
    #pragma unroll
    for (int i = 0; i < 3; i++)
        #pragma unroll
        for (int j = 0; j < 4; j++) pc[i][j] = 0.0f;
    #pragma unroll
    for (int slot = 0; slot < 4; slot++) {
        const int row = roww + (slot >> 1) * 16 + (slot & 1) * 8 + gr;
        const int ci = row / N_ - cmin;
        #pragma unroll
        for (int cs = 0; cs < 3; cs++)
            #pragma unroll
            for (int bs = 0; bs < 4; bs++)
                pc[cs][bs] += (ci == cs) ? pr[slot][bs] : 0.0f;
    }

    #pragma unroll
    for (int cs = 0; cs < 3; cs++) {
        #pragma unroll
        for (int bs = 0; bs < 4; bs++) {
            float v = pc[cs][bs];
            #pragma unroll
            for (int off = 16; off > 0; off >>= 1)
                v += __shfl_xor_sync(0xffffffffu, v, off);
            if (lane == 0) {
                const int c = cmin + cs;
                const int bb = bmin + bs;
                if (c < C_ && bb < B_ && v != 0.0f)
                    atomicAdd(&g_V[bb * C_ + c], v);
            }
        }
    }
}

// ===========================================================================
// Kernel 4: per-b min-max scale.  (R13 exact)
// ===========================================================================
__global__ __launch_bounds__(64) void minmax_kernel(float* __restrict__ out) {
    const int b = blockIdx.x;
    const int t = threadIdx.x;
    const int lane = t & 31;
    const int w = t >> 5;

    __shared__ float sMn[2], sMx[2];

    float v = g_V[b * C_ + t];
    float mn = v, mx = v;
    #pragma unroll
    for (int off = 16; off > 0; off >>= 1) {
        mn = fminf(mn, __shfl_xor_sync(0xffffffffu, mn, off));
        mx = fmaxf(mx, __shfl_xor_sync(0xffffffffu, mx, off));
    }
    if (lane == 0) { sMn[w] = mn; sMx[w] = mx; }
    __syncthreads();
    float gmn = fminf(sMn[0], sMn[1]);
    float gmx = fmaxf(sMx[0], sMx[1]);

    out[b * C_ + t] = (v - gmn) / (gmx - gmn);
}

// ===========================================================================
extern "C" void kernel_launch(void* const* d_in, const int* in_sizes, int n_in,
                              void* d_out, int out_size) {
    const float* x    = (const float*)d_in[0];   // (128, 25, 512)
    const float* high = (const float*)d_in[1];   // (64, 20, 512)
    float* out = (float*)d_out;                  // (128, 64)

    cudaFuncSetAttribute(gemm_kernel,
                         cudaFuncAttributeMaxDynamicSharedMemorySize, SM_TOTAL);

    convert_kernel<<<800, 256>>>(x);
    prep_kernel<<<C_, 256>>>(high);

    dim3 grid(Q_ / BN, M_ROWS / BM);             // (25, 10)
    gemm_kernel<<<grid, 256, SM_TOTAL>>>();

    minmax_kernel<<<B_, 64>>>(out);
}